// round 1
// baseline (speedup 1.0000x reference)
#include <cuda_runtime.h>
#include <cstddef>

#define T_DIM 8192
#define C_DIM 2048

// ---------------- scratch (device globals; no runtime allocation) ----------------
__device__ float g_qkv[(size_t)T_DIM * 3 * C_DIM];   // kerq | kerk | v   (192 MB)
__device__ float g_kv[(size_t)C_DIM * C_DIM];        // K^T V state      (16 MB)
__device__ float g_ksum_part[32 * C_DIM];
__device__ float g_ksum[C_DIM];
__device__ float g_den[T_DIM];
__device__ float g_F[(size_t)T_DIM * C_DIM];         // transposed num/den (64 MB)

// ---------------- generic tiled SGEMM with fused epilogues ----------------
// EPI 0: C = A@B + p0(bias); cols [0,C): (p1*v+p2)^2 ; cols [C,2C): (p3*v+p4)^2 ; else raw
// EPI 1: C = A@B
// EPI 2: C[n*ldc + m] = (A@B)[m][n] / p0[m]   (transposed store, row-scaled)
// EPI 3: C = A@B + p0(bias)
// ATRANS=false: A is [M,K] row-major (lda = row stride)
// ATRANS=true : A is [K,M] (lda = stride over k) -> computes A^T @ B
template<int EPI, bool ATRANS>
__global__ __launch_bounds__(256) void sgemm_kernel(
    const float* __restrict__ A, const float* __restrict__ B, float* __restrict__ C,
    int M, int N, int K, int lda, int ldb, int ldc,
    const float* __restrict__ p0, const float* __restrict__ p1,
    const float* __restrict__ p2, const float* __restrict__ p3,
    const float* __restrict__ p4)
{
    constexpr int BM = 128, BN = 128, BK = 8, TM = 8, TN = 8;
    __shared__ float As[BK][BM];
    __shared__ float Bs[BK][BN];

    const int tid = threadIdx.x;
    const int tx = tid & 15;         // 16 thread-cols
    const int ty = tid >> 4;         // 16 thread-rows
    const int bm0 = blockIdx.y * BM;
    const int bn0 = blockIdx.x * BN;

    float acc[TM][TN] = {};
    float ra[TM], rb[TN];

    for (int k0 = 0; k0 < K; k0 += BK) {
        // ---- load A tile into As[k][m] ----
        if (ATRANS) {
            int k  = tid >> 5;             // 0..7
            int m4 = (tid & 31) * 4;       // 0..124
            float4 v = *reinterpret_cast<const float4*>(
                &A[(size_t)(k0 + k) * lda + bm0 + m4]);
            As[k][m4 + 0] = v.x; As[k][m4 + 1] = v.y;
            As[k][m4 + 2] = v.z; As[k][m4 + 3] = v.w;
        } else {
            int ar = tid >> 1;             // 0..127
            int ac = (tid & 1) * 4;        // 0 or 4
            float4 v = *reinterpret_cast<const float4*>(
                &A[(size_t)(bm0 + ar) * lda + k0 + ac]);
            As[ac + 0][ar] = v.x; As[ac + 1][ar] = v.y;
            As[ac + 2][ar] = v.z; As[ac + 3][ar] = v.w;
        }
        // ---- load B tile into Bs[k][n] ----
        {
            int k  = tid >> 5;
            int n4 = (tid & 31) * 4;
            float4 v = *reinterpret_cast<const float4*>(
                &B[(size_t)(k0 + k) * ldb + bn0 + n4]);
            *reinterpret_cast<float4*>(&Bs[k][n4]) = v;
        }
        __syncthreads();

        #pragma unroll
        for (int k = 0; k < BK; ++k) {
            #pragma unroll
            for (int i = 0; i < TM; i++) ra[i] = As[k][ty * TM + i];
            #pragma unroll
            for (int j = 0; j < TN; j++) rb[j] = Bs[k][tx * TN + j];
            #pragma unroll
            for (int i = 0; i < TM; i++)
                #pragma unroll
                for (int j = 0; j < TN; j++)
                    acc[i][j] += ra[i] * rb[j];
        }
        __syncthreads();
    }

    // ---- epilogue ----
    #pragma unroll
    for (int i = 0; i < TM; i++) {
        const int m = bm0 + ty * TM + i;
        float dinv = 0.f;
        if (EPI == 2) dinv = 1.0f / p0[m];
        #pragma unroll
        for (int j = 0; j < TN; j++) {
            const int n = bn0 + tx * TN + j;
            float val = acc[i][j];
            if (EPI == 0) {
                val += p0[n];
                if (n < C_DIM) {
                    float t = p1[n] * val + p2[n];
                    val = t * t;
                } else if (n < 2 * C_DIM) {
                    int q = n - C_DIM;
                    float t = p3[q] * val + p4[q];
                    val = t * t;
                }
                C[(size_t)m * ldc + n] = val;
            } else if (EPI == 1) {
                C[(size_t)m * ldc + n] = val;
            } else if (EPI == 2) {
                C[(size_t)n * ldc + m] = val * dinv;   // transposed store
            } else {
                C[(size_t)m * ldc + n] = val + p0[n];
            }
        }
    }
}

// ---------------- ksum = sum_t kerk[t][:] ----------------
__global__ __launch_bounds__(256) void ksum_part_kernel(const float* __restrict__ qkv,
                                                        float* __restrict__ part)
{
    const int c = blockIdx.x * 256 + threadIdx.x;
    const float* base = qkv + C_DIM + c;   // kerk column c
    const size_t t0 = (size_t)blockIdx.y * 256;
    float s = 0.f;
    #pragma unroll 8
    for (int i = 0; i < 256; i++) s += base[(t0 + i) * (3 * C_DIM)];
    part[blockIdx.y * C_DIM + c] = s;
}

__global__ __launch_bounds__(256) void ksum_reduce_kernel(const float* __restrict__ part,
                                                          float* __restrict__ ksum)
{
    const int c = blockIdx.x * 256 + threadIdx.x;
    float s = 0.f;
    #pragma unroll
    for (int i = 0; i < 32; i++) s += part[i * C_DIM + c];
    ksum[c] = s;
}

// ---------------- den[t] = kerq[t] . ksum ----------------
__global__ __launch_bounds__(256) void den_kernel(const float* __restrict__ kerq,
                                                  const float* __restrict__ ksum,
                                                  float* __restrict__ den)
{
    __shared__ float ks[C_DIM];
    const int tid = threadIdx.x;
    for (int c = tid; c < C_DIM; c += 256) ks[c] = ksum[c];
    __syncthreads();
    const int warp = tid >> 5, lane = tid & 31;
    const int t = blockIdx.x * 8 + warp;
    const float* row = kerq + (size_t)t * (3 * C_DIM);
    float s = 0.f;
    for (int c = lane; c < C_DIM; c += 32) s += row[c] * ks[c];
    #pragma unroll
    for (int o = 16; o > 0; o >>= 1) s += __shfl_xor_sync(0xffffffffu, s, o);
    if (lane == 0) den[t] = s;
}

// ---------------- launch ----------------
extern "C" void kernel_launch(void* const* d_in, const int* in_sizes, int n_in,
                              void* d_out, int out_size)
{
    const float* x      = (const float*)d_in[0];
    const float* w_attn = (const float*)d_in[1];
    const float* b_attn = (const float*)d_in[2];
    const float* gq     = (const float*)d_in[3];
    const float* bq     = (const float*)d_in[4];
    const float* gk     = (const float*)d_in[5];
    const float* bk     = (const float*)d_in[6];
    const float* w_out  = (const float*)d_in[7];
    const float* b_out  = (const float*)d_in[8];
    float* out = (float*)d_out;

    float *qkv, *kv, *kpart, *ksum, *den, *F;
    cudaGetSymbolAddress((void**)&qkv,   g_qkv);
    cudaGetSymbolAddress((void**)&kv,    g_kv);
    cudaGetSymbolAddress((void**)&kpart, g_ksum_part);
    cudaGetSymbolAddress((void**)&ksum,  g_ksum);
    cudaGetSymbolAddress((void**)&den,   g_den);
    cudaGetSymbolAddress((void**)&F,     g_F);

    const dim3 blk(256);

    // 1) qkv = x @ w_attn + b_attn, fused squared-affine maps -> [kerq|kerk|v]
    sgemm_kernel<0, false><<<dim3(3 * C_DIM / 128, T_DIM / 128), blk>>>(
        x, w_attn, qkv, T_DIM, 3 * C_DIM, C_DIM,
        C_DIM, 3 * C_DIM, 3 * C_DIM, b_attn, gq, bq, gk, bk);

    // 2) ksum = sum_t kerk[t]
    ksum_part_kernel<<<dim3(C_DIM / 256, 32), blk>>>(qkv, kpart);
    ksum_reduce_kernel<<<C_DIM / 256, blk>>>(kpart, ksum);

    // 3) kv = kerk^T @ v   (A stored [K=T, M=C], stride 3C)
    sgemm_kernel<1, true><<<dim3(C_DIM / 128, C_DIM / 128), blk>>>(
        qkv + C_DIM, qkv + 2 * C_DIM, kv, C_DIM, C_DIM, T_DIM,
        3 * C_DIM, 3 * C_DIM, C_DIM, nullptr, nullptr, nullptr, nullptr, nullptr);

    // 4) den[t] = kerq[t] . ksum
    den_kernel<<<T_DIM / 8, blk>>>(qkv, ksum, den);

    // 5) num/den with transposed store: F_flat[c*T + t] = (kerq@kv)[t][c] / den[t]
    sgemm_kernel<2, false><<<dim3(C_DIM / 128, T_DIM / 128), blk>>>(
        qkv, kv, F, T_DIM, C_DIM, C_DIM,
        3 * C_DIM, C_DIM, T_DIM, den, nullptr, nullptr, nullptr, nullptr);

    // 6) out = F @ w_out + b_out   (F read back as row-major [T, C] == the
    //    transpose(0,2,1).reshape(T,C) reinterpretation of num/den)
    sgemm_kernel<3, false><<<dim3(C_DIM / 128, T_DIM / 128), blk>>>(
        F, w_out, out, T_DIM, C_DIM, C_DIM,
        C_DIM, C_DIM, C_DIM, b_out, nullptr, nullptr, nullptr, nullptr);
}

// round 5
// speedup vs baseline: 2.0346x; 2.0346x over previous
#include <cuda_runtime.h>
#include <cuda_bf16.h>
#include <cstdint>
#include <cstddef>

#define T_DIM 8192
#define C_DIM 2048

// ---------------- scratch (device globals; no runtime allocation) ----------------
__device__ float g_qkv[(size_t)T_DIM * 3 * C_DIM];      // kerq | kerk | v  (192 MB)
__device__ float g_kvT[(size_t)C_DIM * C_DIM];          // kv^T [d][c]      (16 MB)
__device__ float g_ksum_part[32 * C_DIM];
__device__ float g_ksum[C_DIM];
__device__ float g_den[T_DIM];
__device__ float g_F[(size_t)T_DIM * C_DIM];            // transposed num/den (64 MB)
__device__ float g_wattnT[(size_t)3 * C_DIM * C_DIM];   // [3C, C]  (48 MB)
__device__ float g_woutT[(size_t)C_DIM * C_DIM];        // [C, C]   (16 MB)
__device__ float g_kerkT[(size_t)C_DIM * T_DIM];        // [C, T]   (64 MB)
__device__ float g_vT[(size_t)C_DIM * T_DIM];           // [C, T]   (64 MB)

// ---------------- warp-MMA helpers (baseline PTX, compiles for sm_100) ----------------
__device__ __forceinline__ uint32_t smem_u32_of(const void* p) {
    uint32_t a;
    asm("{ .reg .u64 t; cvta.to.shared.u64 t, %1; cvt.u32.u64 %0, t; }" : "=r"(a) : "l"(p));
    return a;
}
__device__ __forceinline__ void ldsm_x4(uint32_t& r0, uint32_t& r1, uint32_t& r2, uint32_t& r3,
                                        uint32_t addr) {
    asm volatile("ldmatrix.sync.aligned.m8n8.x4.shared.b16 {%0,%1,%2,%3}, [%4];"
                 : "=r"(r0), "=r"(r1), "=r"(r2), "=r"(r3) : "r"(addr));
}
__device__ __forceinline__ void mma16816(float* d, const uint32_t* a, const uint32_t* b) {
    asm volatile(
        "mma.sync.aligned.m16n8k16.row.col.f32.bf16.bf16.f32 "
        "{%0,%1,%2,%3}, {%4,%5,%6,%7}, {%8,%9}, {%0,%1,%2,%3};"
        : "+f"(d[0]), "+f"(d[1]), "+f"(d[2]), "+f"(d[3])
        : "r"(a[0]), "r"(a[1]), "r"(a[2]), "r"(a[3]), "r"(b[0]), "r"(b[1]));
}

// split fp32 -> bf16 hi + bf16 lo, 4 at a time, 8-byte stores
__device__ __forceinline__ void split4(__nv_bfloat16* hp, __nv_bfloat16* lp, float4 v) {
    __nv_bfloat16 h0 = __float2bfloat16_rn(v.x), h1 = __float2bfloat16_rn(v.y),
                  h2 = __float2bfloat16_rn(v.z), h3 = __float2bfloat16_rn(v.w);
    float l0 = v.x - __bfloat162float(h0), l1 = v.y - __bfloat162float(h1);
    float l2 = v.z - __bfloat162float(h2), l3 = v.w - __bfloat162float(h3);
    __nv_bfloat16 g0 = __float2bfloat16_rn(l0), g1 = __float2bfloat16_rn(l1),
                  g2 = __float2bfloat16_rn(l2), g3 = __float2bfloat16_rn(l3);
    uint2 H, L;
    H.x = ((uint32_t)__bfloat16_as_ushort(h1) << 16) | __bfloat16_as_ushort(h0);
    H.y = ((uint32_t)__bfloat16_as_ushort(h3) << 16) | __bfloat16_as_ushort(h2);
    L.x = ((uint32_t)__bfloat16_as_ushort(g1) << 16) | __bfloat16_as_ushort(g0);
    L.y = ((uint32_t)__bfloat16_as_ushort(g3) << 16) | __bfloat16_as_ushort(g2);
    *reinterpret_cast<uint2*>(hp) = H;
    *reinterpret_cast<uint2*>(lp) = L;
}

// ---------------- tensor-core GEMM: D = A @ B^T, split-bf16 x3 ----------------
// A: [M,K] row-major (lda). B: [N,K] row-major (ldb). M%128==0, N%128==0, K%32==0.
// grid = (N/128, M/128), block = 256 (8 warps, 2x4 warp grid, warp tile 64x32).
// EPI 0: C[m][n] = maps(acc + p0[n])   (squared affine on first two C_DIM col-blocks)
// EPI 1: C[m][n] = acc
// EPI 2: C[n*ldc + m] = acc / p0[m]    (transposed store)
// EPI 3: C[m][n] = acc + p0[n]
static constexpr int LDT = 40;                   // halves per smem row (pad 8)
static constexpr int MATB = 128 * LDT * 2;       // bytes per matrix = 10240
static constexpr int STAGEB = 4 * MATB;          // Ah|Al|Bh|Bl = 40960
static constexpr int SMEM_TOTAL = 2 * STAGEB;    // 81920

template<int EPI>
__global__ __launch_bounds__(256, 1) void tc_gemm(
    const float* __restrict__ A, const float* __restrict__ B, float* __restrict__ C,
    int K, int lda, int ldb, int ldc,
    const float* __restrict__ p0, const float* __restrict__ p1,
    const float* __restrict__ p2, const float* __restrict__ p3,
    const float* __restrict__ p4)
{
    extern __shared__ __align__(16) char smem[];
    const uint32_t su = smem_u32_of(smem);
    __nv_bfloat16* sh = reinterpret_cast<__nv_bfloat16*>(smem);

    const int tid = threadIdx.x;
    const int wid = tid >> 5, lane = tid & 31;
    const int wm = wid >> 2, wn = wid & 3;       // 2 x 4 warp grid
    const int bm0 = blockIdx.y * 128;
    const int bn0 = blockIdx.x * 128;

    float acc[4][4][4];
    #pragma unroll
    for (int i = 0; i < 4; i++)
        #pragma unroll
        for (int j = 0; j < 4; j++)
            #pragma unroll
            for (int e = 0; e < 4; e++) acc[i][j][e] = 0.f;

    // per-thread load coords: 8 float4 per 128x32 tile row
    const int lr = tid >> 3;          // 0..31 (plus i*32)
    const int lc = tid & 7;           // float4 index in row
    float4 stA[4], stB[4];

    auto ldg = [&](int c) {
        const int k0 = c * 32;
        #pragma unroll
        for (int i = 0; i < 4; i++)
            stA[i] = *reinterpret_cast<const float4*>(&A[(size_t)(bm0 + i * 32 + lr) * lda + k0 + lc * 4]);
        #pragma unroll
        for (int i = 0; i < 4; i++)
            stB[i] = *reinterpret_cast<const float4*>(&B[(size_t)(bn0 + i * 32 + lr) * ldb + k0 + lc * 4]);
    };
    auto sts = [&](int buf) {
        __nv_bfloat16* base = sh + buf * (STAGEB / 2);
        #pragma unroll
        for (int i = 0; i < 4; i++) {
            int off = (i * 32 + lr) * LDT + lc * 4;
            split4(base + off, base + MATB / 2 + off, stA[i]);                       // Ah, Al
            split4(base + 2 * (MATB / 2) + off, base + 3 * (MATB / 2) + off, stB[i]); // Bh, Bl
        }
    };

    const int nch = K / 32;
    ldg(0);
    for (int c = 0; c < nch; c++) {
        const int buf = c & 1;
        sts(buf);
        __syncthreads();
        if (c + 1 < nch) ldg(c + 1);

        const uint32_t sb = su + buf * STAGEB;
        const uint32_t aoff = sb + ((wm * 64 + (lane & 15)) * LDT + (lane >> 4) * 8) * 2;
        const uint32_t boff = sb + 2 * MATB +
            ((wn * 32 + (lane & 7) + ((lane >> 4) << 3)) * LDT + ((lane >> 3) & 1) * 8) * 2;

        #pragma unroll
        for (int ks = 0; ks < 2; ks++) {
            uint32_t bh[4][2], bl[4][2];
            #pragma unroll
            for (int nb = 0; nb < 2; nb++) {
                uint32_t addr = boff + (nb * 16 * LDT + ks * 16) * 2;
                ldsm_x4(bh[nb * 2][0], bh[nb * 2][1], bh[nb * 2 + 1][0], bh[nb * 2 + 1][1], addr);
                ldsm_x4(bl[nb * 2][0], bl[nb * 2][1], bl[nb * 2 + 1][0], bl[nb * 2 + 1][1], addr + MATB);
            }
            #pragma unroll
            for (int mi = 0; mi < 4; mi++) {
                uint32_t ah[4], al[4];
                uint32_t addr = aoff + (mi * 16 * LDT + ks * 16) * 2;
                ldsm_x4(ah[0], ah[1], ah[2], ah[3], addr);
                ldsm_x4(al[0], al[1], al[2], al[3], addr + MATB);
                #pragma unroll
                for (int ni = 0; ni < 4; ni++) {
                    mma16816(acc[mi][ni], ah, bh[ni]);
                    mma16816(acc[mi][ni], ah, bl[ni]);
                    mma16816(acc[mi][ni], al, bh[ni]);
                }
            }
        }
        __syncthreads();
    }

    // ---- epilogue: acc[mi][ni] covers rows {r0, r0+8}, cols {c0, c0+1} ----
    #pragma unroll
    for (int mi = 0; mi < 4; mi++) {
        const int r0 = bm0 + wm * 64 + mi * 16 + (lane >> 2);
        float d0 = 0.f, d1 = 0.f;
        if (EPI == 2) { d0 = 1.0f / p0[r0]; d1 = 1.0f / p0[r0 + 8]; }
        #pragma unroll
        for (int ni = 0; ni < 4; ni++) {
            const int c0 = bn0 + wn * 32 + ni * 8 + (lane & 3) * 2;
            #pragma unroll
            for (int e = 0; e < 4; e++) {
                const int m = r0 + ((e >> 1) << 3);
                const int n = c0 + (e & 1);
                float val = acc[mi][ni][e];
                if (EPI == 0) {
                    val += p0[n];
                    if (n < C_DIM) { float t = p1[n] * val + p2[n]; val = t * t; }
                    else if (n < 2 * C_DIM) { int q = n - C_DIM; float t = p3[q] * val + p4[q]; val = t * t; }
                    C[(size_t)m * ldc + n] = val;
                } else if (EPI == 1) {
                    C[(size_t)m * ldc + n] = val;
                } else if (EPI == 2) {
                    C[(size_t)n * ldc + m] = val * ((e >> 1) ? d1 : d0);
                } else {
                    C[(size_t)m * ldc + n] = val + p0[n];
                }
            }
        }
    }
}

// ---------------- transpose: dst[c][r] = src[r][c] ----------------
__global__ __launch_bounds__(256) void transpose_k(const float* __restrict__ src,
                                                   float* __restrict__ dst,
                                                   int lds, int ldd)
{
    __shared__ float t[32][33];
    const int cb = blockIdx.x * 32, rb = blockIdx.y * 32;
    const int x = threadIdx.x, y = threadIdx.y;
    #pragma unroll
    for (int i = 0; i < 32; i += 8)
        t[y + i][x] = src[(size_t)(rb + y + i) * lds + cb + x];
    __syncthreads();
    #pragma unroll
    for (int i = 0; i < 32; i += 8)
        dst[(size_t)(cb + y + i) * ldd + rb + x] = t[x][y + i];
}

// ---------------- ksum / den (fp32, cheap) ----------------
__global__ __launch_bounds__(256) void ksum_part_kernel(const float* __restrict__ qkv,
                                                        float* __restrict__ part)
{
    const int c = blockIdx.x * 256 + threadIdx.x;
    const float* base = qkv + C_DIM + c;
    const size_t t0 = (size_t)blockIdx.y * 256;
    float s = 0.f;
    #pragma unroll 8
    for (int i = 0; i < 256; i++) s += base[(t0 + i) * (3 * C_DIM)];
    part[blockIdx.y * C_DIM + c] = s;
}
__global__ __launch_bounds__(256) void ksum_reduce_kernel(const float* __restrict__ part,
                                                          float* __restrict__ ksum)
{
    const int c = blockIdx.x * 256 + threadIdx.x;
    float s = 0.f;
    #pragma unroll
    for (int i = 0; i < 32; i++) s += part[i * C_DIM + c];
    ksum[c] = s;
}
__global__ __launch_bounds__(256) void den_kernel(const float* __restrict__ kerq,
                                                  const float* __restrict__ ksum,
                                                  float* __restrict__ den)
{
    __shared__ float ks[C_DIM];
    const int tid = threadIdx.x;
    for (int c = tid; c < C_DIM; c += 256) ks[c] = ksum[c];
    __syncthreads();
    const int warp = tid >> 5, lane = tid & 31;
    const int t = blockIdx.x * 8 + warp;
    const float* row = kerq + (size_t)t * (3 * C_DIM);
    float s = 0.f;
    for (int c = lane; c < C_DIM; c += 32) s += row[c] * ks[c];
    #pragma unroll
    for (int o = 16; o > 0; o >>= 1) s += __shfl_xor_sync(0xffffffffu, s, o);
    if (lane == 0) den[t] = s;
}

// ---------------- launch ----------------
extern "C" void kernel_launch(void* const* d_in, const int* in_sizes, int n_in,
                              void* d_out, int out_size)
{
    const float* x      = (const float*)d_in[0];
    const float* w_attn = (const float*)d_in[1];
    const float* b_attn = (const float*)d_in[2];
    const float* gq     = (const float*)d_in[3];
    const float* bq     = (const float*)d_in[4];
    const float* gk     = (const float*)d_in[5];
    const float* bk     = (const float*)d_in[6];
    const float* w_out  = (const float*)d_in[7];
    const float* b_out  = (const float*)d_in[8];
    float* out = (float*)d_out;

    float *qkv, *kvT, *kpart, *ksum, *den, *F, *wattnT, *woutT, *kerkT, *vT;
    cudaGetSymbolAddress((void**)&qkv,    g_qkv);
    cudaGetSymbolAddress((void**)&kvT,    g_kvT);
    cudaGetSymbolAddress((void**)&kpart,  g_ksum_part);
    cudaGetSymbolAddress((void**)&ksum,   g_ksum);
    cudaGetSymbolAddress((void**)&den,    g_den);
    cudaGetSymbolAddress((void**)&F,      g_F);
    cudaGetSymbolAddress((void**)&wattnT, g_wattnT);
    cudaGetSymbolAddress((void**)&woutT,  g_woutT);
    cudaGetSymbolAddress((void**)&kerkT,  g_kerkT);
    cudaGetSymbolAddress((void**)&vT,     g_vT);

    cudaFuncSetAttribute(tc_gemm<0>, cudaFuncAttributeMaxDynamicSharedMemorySize, SMEM_TOTAL);
    cudaFuncSetAttribute(tc_gemm<1>, cudaFuncAttributeMaxDynamicSharedMemorySize, SMEM_TOTAL);
    cudaFuncSetAttribute(tc_gemm<2>, cudaFuncAttributeMaxDynamicSharedMemorySize, SMEM_TOTAL);
    cudaFuncSetAttribute(tc_gemm<3>, cudaFuncAttributeMaxDynamicSharedMemorySize, SMEM_TOTAL);

    const dim3 tb(32, 8);

    // weight transposes
    transpose_k<<<dim3(3 * C_DIM / 32, C_DIM / 32), tb>>>(w_attn, wattnT, 3 * C_DIM, C_DIM);
    transpose_k<<<dim3(C_DIM / 32, C_DIM / 32), tb>>>(w_out, woutT, C_DIM, C_DIM);

    // 1) qkv = x @ w_attn + b_attn, fused squared-affine maps
    tc_gemm<0><<<dim3(3 * C_DIM / 128, T_DIM / 128), 256, SMEM_TOTAL>>>(
        x, wattnT, qkv, C_DIM, C_DIM, C_DIM, 3 * C_DIM, b_attn, gq, bq, gk, bk);

    // 2) ksum
    ksum_part_kernel<<<dim3(C_DIM / 256, 32), 256>>>(qkv, kpart);
    ksum_reduce_kernel<<<C_DIM / 256, 256>>>(kpart, ksum);

    // transposes of kerk, v -> [C, T]
    transpose_k<<<dim3(C_DIM / 32, T_DIM / 32), tb>>>(qkv + C_DIM, kerkT, 3 * C_DIM, T_DIM);
    transpose_k<<<dim3(C_DIM / 32, T_DIM / 32), tb>>>(qkv + 2 * C_DIM, vT, 3 * C_DIM, T_DIM);

    // 3) kvT[d][c] = sum_t vT[d][t] * kerkT[c][t]
    tc_gemm<1><<<dim3(C_DIM / 128, C_DIM / 128), 256, SMEM_TOTAL>>>(
        vT, kerkT, kvT, T_DIM, T_DIM, T_DIM, C_DIM,
        nullptr, nullptr, nullptr, nullptr, nullptr);

    // 4) den[t] = kerq[t] . ksum
    den_kernel<<<T_DIM / 8, 256>>>(qkv, ksum, den);

    // 5) num/den, transposed store: F_flat[n*T + m] = (kerq@kv)[m][n] / den[m]
    tc_gemm<2><<<dim3(C_DIM / 128, T_DIM / 128), 256, SMEM_TOTAL>>>(
        qkv, kvT, F, C_DIM, 3 * C_DIM, C_DIM, T_DIM,
        den, nullptr, nullptr, nullptr, nullptr);

    // 6) out = F2 @ w_out + b_out  (F reinterpreted as [T, C] row-major)
    tc_gemm<3><<<dim3(C_DIM / 128, T_DIM / 128), 256, SMEM_TOTAL>>>(
        F, woutT, out, C_DIM, C_DIM, C_DIM, C_DIM,
        b_out, nullptr, nullptr, nullptr, nullptr);
}

// round 6
// speedup vs baseline: 2.0548x; 1.0099x over previous
#include <cuda_runtime.h>
#include <cuda_bf16.h>
#include <cstdint>
#include <cstddef>

#define T_DIM 8192
#define C_DIM 2048

// ---------------- scratch (device globals; no runtime allocation) ----------------
__device__ float g_qkv[(size_t)T_DIM * 3 * C_DIM];      // kerq | kerk | v  (192 MB)
__device__ float g_kvT[(size_t)C_DIM * C_DIM];          // kv^T [d][c]      (16 MB)
__device__ float g_ksum_part[32 * C_DIM];
__device__ float g_ksum[C_DIM];
__device__ float g_den[T_DIM];
__device__ float g_F[(size_t)T_DIM * C_DIM];            // transposed num/den (64 MB)
__device__ float g_wattnT[(size_t)3 * C_DIM * C_DIM];   // [3C, C]  (48 MB)
__device__ float g_woutT[(size_t)C_DIM * C_DIM];        // [C, C]   (16 MB)

// ---------------- warp-MMA helpers (baseline PTX, compiles for sm_100) ----------------
__device__ __forceinline__ uint32_t smem_u32_of(const void* p) {
    uint32_t a;
    asm("{ .reg .u64 t; cvta.to.shared.u64 t, %1; cvt.u32.u64 %0, t; }" : "=r"(a) : "l"(p));
    return a;
}
__device__ __forceinline__ void ldsm_x4(uint32_t& r0, uint32_t& r1, uint32_t& r2, uint32_t& r3,
                                        uint32_t addr) {
    asm volatile("ldmatrix.sync.aligned.m8n8.x4.shared.b16 {%0,%1,%2,%3}, [%4];"
                 : "=r"(r0), "=r"(r1), "=r"(r2), "=r"(r3) : "r"(addr));
}
__device__ __forceinline__ void mma16816(float* d, const uint32_t* a, const uint32_t* b) {
    asm volatile(
        "mma.sync.aligned.m16n8k16.row.col.f32.bf16.bf16.f32 "
        "{%0,%1,%2,%3}, {%4,%5,%6,%7}, {%8,%9}, {%0,%1,%2,%3};"
        : "+f"(d[0]), "+f"(d[1]), "+f"(d[2]), "+f"(d[3])
        : "r"(a[0]), "r"(a[1]), "r"(a[2]), "r"(a[3]), "r"(b[0]), "r"(b[1]));
}

// split fp32 -> bf16 hi + bf16 lo, 4 at a time, 8-byte stores
__device__ __forceinline__ void split4(__nv_bfloat16* hp, __nv_bfloat16* lp, float4 v) {
    __nv_bfloat16 h0 = __float2bfloat16_rn(v.x), h1 = __float2bfloat16_rn(v.y),
                  h2 = __float2bfloat16_rn(v.z), h3 = __float2bfloat16_rn(v.w);
    float l0 = v.x - __bfloat162float(h0), l1 = v.y - __bfloat162float(h1);
    float l2 = v.z - __bfloat162float(h2), l3 = v.w - __bfloat162float(h3);
    __nv_bfloat16 g0 = __float2bfloat16_rn(l0), g1 = __float2bfloat16_rn(l1),
                  g2 = __float2bfloat16_rn(l2), g3 = __float2bfloat16_rn(l3);
    uint2 H, L;
    H.x = ((uint32_t)__bfloat16_as_ushort(h1) << 16) | __bfloat16_as_ushort(h0);
    H.y = ((uint32_t)__bfloat16_as_ushort(h3) << 16) | __bfloat16_as_ushort(h2);
    L.x = ((uint32_t)__bfloat16_as_ushort(g1) << 16) | __bfloat16_as_ushort(g0);
    L.y = ((uint32_t)__bfloat16_as_ushort(g3) << 16) | __bfloat16_as_ushort(g2);
    *reinterpret_cast<uint2*>(hp) = H;
    *reinterpret_cast<uint2*>(lp) = L;
}
// scalar split for transposed stores
__device__ __forceinline__ void split1(__nv_bfloat16* hp, __nv_bfloat16* lp, float v) {
    __nv_bfloat16 h = __float2bfloat16_rn(v);
    __nv_bfloat16 l = __float2bfloat16_rn(v - __bfloat162float(h));
    *hp = h; *lp = l;
}

// ---------------- tensor-core GEMM: D = A @ B^T, split-bf16 x3 ----------------
// TRANS=false: A [M,K] row-major (lda = row stride), B [N,K] row-major.
// TRANS=true : A [K,M] (lda = k-row stride), B [K,N] -> same math, in-place transposed read.
// grid = (N/128, M/128), block = 256 (8 warps, 2x4 warp grid, warp tile 64x32).
// EPI 0: C[m][n] = maps(acc + p0[n]); EPI 1: raw; EPI 2: C[n*ldc+m] = acc/p0[m]; EPI 3: +p0[n]
static constexpr int LDT = 40;                   // halves per smem row (pad 8)
static constexpr int MATB = 128 * LDT * 2;       // bytes per matrix = 10240
static constexpr int STAGEB = 4 * MATB;          // Ah|Al|Bh|Bl = 40960
static constexpr int SMEM_TOTAL = 2 * STAGEB;    // 81920

template<int EPI, bool TRANS>
__global__ __launch_bounds__(256, 1) void tc_gemm(
    const float* __restrict__ A, const float* __restrict__ B, float* __restrict__ C,
    int K, int lda, int ldb, int ldc,
    const float* __restrict__ p0, const float* __restrict__ p1,
    const float* __restrict__ p2, const float* __restrict__ p3,
    const float* __restrict__ p4)
{
    extern __shared__ __align__(16) char smem[];
    const uint32_t su = smem_u32_of(smem);
    __nv_bfloat16* sh = reinterpret_cast<__nv_bfloat16*>(smem);

    const int tid = threadIdx.x;
    const int wid = tid >> 5, lane = tid & 31;
    const int wm = wid >> 2, wn = wid & 3;       // 2 x 4 warp grid
    const int bm0 = blockIdx.y * 128;
    const int bn0 = blockIdx.x * 128;

    float acc[4][4][4];
    #pragma unroll
    for (int i = 0; i < 4; i++)
        #pragma unroll
        for (int j = 0; j < 4; j++)
            #pragma unroll
            for (int e = 0; e < 4; e++) acc[i][j][e] = 0.f;

    const int lr = tid >> 3;          // 0..31
    const int lc = tid & 7;           // float4 index
    float4 stA[4], stB[4];

    auto ldg = [&](int c) {
        const int k0 = c * 32;
        if (!TRANS) {
            #pragma unroll
            for (int i = 0; i < 4; i++)
                stA[i] = *reinterpret_cast<const float4*>(&A[(size_t)(bm0 + i * 32 + lr) * lda + k0 + lc * 4]);
            #pragma unroll
            for (int i = 0; i < 4; i++)
                stB[i] = *reinterpret_cast<const float4*>(&B[(size_t)(bn0 + i * 32 + lr) * ldb + k0 + lc * 4]);
        } else {
            // lr = k row within chunk, elements are contiguous along m/n
            #pragma unroll
            for (int i = 0; i < 4; i++)
                stA[i] = *reinterpret_cast<const float4*>(&A[(size_t)(k0 + lr) * lda + bm0 + i * 32 + lc * 4]);
            #pragma unroll
            for (int i = 0; i < 4; i++)
                stB[i] = *reinterpret_cast<const float4*>(&B[(size_t)(k0 + lr) * ldb + bn0 + i * 32 + lc * 4]);
        }
    };
    auto sts = [&](int buf) {
        __nv_bfloat16* base = sh + buf * (STAGEB / 2);
        if (!TRANS) {
            #pragma unroll
            for (int i = 0; i < 4; i++) {
                int off = (i * 32 + lr) * LDT + lc * 4;
                split4(base + off, base + MATB / 2 + off, stA[i]);
                split4(base + 2 * (MATB / 2) + off, base + 3 * (MATB / 2) + off, stB[i]);
            }
        } else {
            // thread holds (k=lr, m = i*32+lc*4+j): scatter into [m][k] layout
            #pragma unroll
            for (int i = 0; i < 4; i++) {
                const float va[4] = {stA[i].x, stA[i].y, stA[i].z, stA[i].w};
                const float vb[4] = {stB[i].x, stB[i].y, stB[i].z, stB[i].w};
                #pragma unroll
                for (int j = 0; j < 4; j++) {
                    int off = (i * 32 + lc * 4 + j) * LDT + lr;
                    split1(base + off, base + MATB / 2 + off, va[j]);
                    split1(base + 2 * (MATB / 2) + off, base + 3 * (MATB / 2) + off, vb[j]);
                }
            }
        }
    };

    const int nch = K / 32;
    ldg(0);
    sts(0);
    __syncthreads();
    if (nch > 1) ldg(1);

    for (int c = 0; c < nch; c++) {
        const int buf = c & 1;
        const uint32_t sb = su + buf * STAGEB;
        const uint32_t aoff = sb + ((wm * 64 + (lane & 15)) * LDT + (lane >> 4) * 8) * 2;
        const uint32_t boff = sb + 2 * MATB +
            ((wn * 32 + (lane & 7) + ((lane >> 4) << 3)) * LDT + ((lane >> 3) & 1) * 8) * 2;

        #pragma unroll
        for (int ks = 0; ks < 2; ks++) {
            uint32_t bh[4][2], bl[4][2];
            #pragma unroll
            for (int nb = 0; nb < 2; nb++) {
                uint32_t addr = boff + (nb * 16 * LDT + ks * 16) * 2;
                ldsm_x4(bh[nb * 2][0], bh[nb * 2][1], bh[nb * 2 + 1][0], bh[nb * 2 + 1][1], addr);
                ldsm_x4(bl[nb * 2][0], bl[nb * 2][1], bl[nb * 2 + 1][0], bl[nb * 2 + 1][1], addr + MATB);
            }
            #pragma unroll
            for (int mi = 0; mi < 4; mi++) {
                uint32_t ah[4], al[4];
                uint32_t addr = aoff + (mi * 16 * LDT + ks * 16) * 2;
                ldsm_x4(ah[0], ah[1], ah[2], ah[3], addr);
                ldsm_x4(al[0], al[1], al[2], al[3], addr + MATB);
                #pragma unroll
                for (int ni = 0; ni < 4; ni++) {
                    mma16816(acc[mi][ni], ah, bh[ni]);
                    mma16816(acc[mi][ni], ah, bl[ni]);
                    mma16816(acc[mi][ni], al, bh[ni]);
                }
            }
        }

        // write the NEXT chunk into the other buffer (its last readers synced at end of c-1),
        // then prefetch chunk c+2 into registers
        if (c + 1 < nch) {
            sts(buf ^ 1);
            __syncthreads();
            if (c + 2 < nch) ldg(c + 2);
        }
    }

    // ---- epilogue ----
    #pragma unroll
    for (int mi = 0; mi < 4; mi++) {
        const int r0 = bm0 + wm * 64 + mi * 16 + (lane >> 2);
        float d0 = 0.f, d1 = 0.f;
        if (EPI == 2) { d0 = 1.0f / p0[r0]; d1 = 1.0f / p0[r0 + 8]; }
        #pragma unroll
        for (int ni = 0; ni < 4; ni++) {
            const int c0 = bn0 + wn * 32 + ni * 8 + (lane & 3) * 2;
            #pragma unroll
            for (int e = 0; e < 4; e++) {
                const int m = r0 + ((e >> 1) << 3);
                const int n = c0 + (e & 1);
                float val = acc[mi][ni][e];
                if (EPI == 0) {
                    val += p0[n];
                    if (n < C_DIM) { float t = p1[n] * val + p2[n]; val = t * t; }
                    else if (n < 2 * C_DIM) { int q = n - C_DIM; float t = p3[q] * val + p4[q]; val = t * t; }
                    C[(size_t)m * ldc + n] = val;
                } else if (EPI == 1) {
                    C[(size_t)m * ldc + n] = val;
                } else if (EPI == 2) {
                    C[(size_t)n * ldc + m] = val * ((e >> 1) ? d1 : d0);
                } else {
                    C[(size_t)m * ldc + n] = val + p0[n];
                }
            }
        }
    }
}

// ---------------- transpose: dst[c][r] = src[r][c] (weights only) ----------------
__global__ __launch_bounds__(256) void transpose_k(const float* __restrict__ src,
                                                   float* __restrict__ dst,
                                                   int lds, int ldd)
{
    __shared__ float t[32][33];
    const int cb = blockIdx.x * 32, rb = blockIdx.y * 32;
    const int x = threadIdx.x, y = threadIdx.y;
    #pragma unroll
    for (int i = 0; i < 32; i += 8)
        t[y + i][x] = src[(size_t)(rb + y + i) * lds + cb + x];
    __syncthreads();
    #pragma unroll
    for (int i = 0; i < 32; i += 8)
        dst[(size_t)(cb + y + i) * ldd + rb + x] = t[x][y + i];
}

// ---------------- ksum / den (fp32, cheap) ----------------
__global__ __launch_bounds__(256) void ksum_part_kernel(const float* __restrict__ qkv,
                                                        float* __restrict__ part)
{
    const int c = blockIdx.x * 256 + threadIdx.x;
    const float* base = qkv + C_DIM + c;
    const size_t t0 = (size_t)blockIdx.y * 256;
    float s = 0.f;
    #pragma unroll 8
    for (int i = 0; i < 256; i++) s += base[(t0 + i) * (3 * C_DIM)];
    part[blockIdx.y * C_DIM + c] = s;
}
__global__ __launch_bounds__(256) void ksum_reduce_kernel(const float* __restrict__ part,
                                                          float* __restrict__ ksum)
{
    const int c = blockIdx.x * 256 + threadIdx.x;
    float s = 0.f;
    #pragma unroll
    for (int i = 0; i < 32; i++) s += part[i * C_DIM + c];
    ksum[c] = s;
}
__global__ __launch_bounds__(256) void den_kernel(const float* __restrict__ kerq,
                                                  const float* __restrict__ ksum,
                                                  float* __restrict__ den)
{
    __shared__ float ks[C_DIM];
    const int tid = threadIdx.x;
    for (int c = tid; c < C_DIM; c += 256) ks[c] = ksum[c];
    __syncthreads();
    const int warp = tid >> 5, lane = tid & 31;
    const int t = blockIdx.x * 8 + warp;
    const float* row = kerq + (size_t)t * (3 * C_DIM);
    float s = 0.f;
    for (int c = lane; c < C_DIM; c += 32) s += row[c] * ks[c];
    #pragma unroll
    for (int o = 16; o > 0; o >>= 1) s += __shfl_xor_sync(0xffffffffu, s, o);
    if (lane == 0) den[t] = s;
}

// ---------------- launch ----------------
extern "C" void kernel_launch(void* const* d_in, const int* in_sizes, int n_in,
                              void* d_out, int out_size)
{
    const float* x      = (const float*)d_in[0];
    const float* w_attn = (const float*)d_in[1];
    const float* b_attn = (const float*)d_in[2];
    const float* gq     = (const float*)d_in[3];
    const float* bq     = (const float*)d_in[4];
    const float* gk     = (const float*)d_in[5];
    const float* bk     = (const float*)d_in[6];
    const float* w_out  = (const float*)d_in[7];
    const float* b_out  = (const float*)d_in[8];
    float* out = (float*)d_out;

    float *qkv, *kvT, *kpart, *ksum, *den, *F, *wattnT, *woutT;
    cudaGetSymbolAddress((void**)&qkv,    g_qkv);
    cudaGetSymbolAddress((void**)&kvT,    g_kvT);
    cudaGetSymbolAddress((void**)&kpart,  g_ksum_part);
    cudaGetSymbolAddress((void**)&ksum,   g_ksum);
    cudaGetSymbolAddress((void**)&den,    g_den);
    cudaGetSymbolAddress((void**)&F,      g_F);
    cudaGetSymbolAddress((void**)&wattnT, g_wattnT);
    cudaGetSymbolAddress((void**)&woutT,  g_woutT);

    cudaFuncSetAttribute(tc_gemm<0,false>, cudaFuncAttributeMaxDynamicSharedMemorySize, SMEM_TOTAL);
    cudaFuncSetAttribute(tc_gemm<1,true>,  cudaFuncAttributeMaxDynamicSharedMemorySize, SMEM_TOTAL);
    cudaFuncSetAttribute(tc_gemm<2,false>, cudaFuncAttributeMaxDynamicSharedMemorySize, SMEM_TOTAL);
    cudaFuncSetAttribute(tc_gemm<3,false>, cudaFuncAttributeMaxDynamicSharedMemorySize, SMEM_TOTAL);

    const dim3 tb(32, 8);

    // weight transposes (cheap one-time; amortized over 48/16 reuses)
    transpose_k<<<dim3(3 * C_DIM / 32, C_DIM / 32), tb>>>(w_attn, wattnT, 3 * C_DIM, C_DIM);
    transpose_k<<<dim3(C_DIM / 32, C_DIM / 32), tb>>>(w_out, woutT, C_DIM, C_DIM);

    // 1) qkv = x @ w_attn + b_attn, fused squared-affine maps
    tc_gemm<0,false><<<dim3(3 * C_DIM / 128, T_DIM / 128), 256, SMEM_TOTAL>>>(
        x, wattnT, qkv, C_DIM, C_DIM, C_DIM, 3 * C_DIM, b_attn, gq, bq, gk, bk);

    // 2) ksum
    ksum_part_kernel<<<dim3(C_DIM / 256, 32), 256>>>(qkv, kpart);
    ksum_reduce_kernel<<<C_DIM / 256, 256>>>(kpart, ksum);

    // 3) kvT[d][c] = sum_t v[t][d] * kerk[t][c]  — in-place transposed reads, no scratch
    tc_gemm<1,true><<<dim3(C_DIM / 128, C_DIM / 128), 256, SMEM_TOTAL>>>(
        qkv + 2 * C_DIM, qkv + C_DIM, kvT, T_DIM, 3 * C_DIM, 3 * C_DIM, C_DIM,
        nullptr, nullptr, nullptr, nullptr, nullptr);

    // 4) den[t] = kerq[t] . ksum
    den_kernel<<<T_DIM / 8, 256>>>(qkv, ksum, den);

    // 5) num/den, transposed store: F_flat[n*T + m] = (kerq@kv)[m][n] / den[m]
    tc_gemm<2,false><<<dim3(C_DIM / 128, T_DIM / 128), 256, SMEM_TOTAL>>>(
        qkv, kvT, F, C_DIM, 3 * C_DIM, C_DIM, T_DIM,
        den, nullptr, nullptr, nullptr, nullptr);

    // 6) out = F2 @ w_out + b_out  (F reinterpreted as [T, C] row-major)
    tc_gemm<3,false><<<dim3(C_DIM / 128, T_DIM / 128), 256, SMEM_TOTAL>>>(
        F, woutT, out, C_DIM, C_DIM, C_DIM, C_DIM,
        b_out, nullptr, nullptr, nullptr, nullptr);
}